// round 2
// baseline (speedup 1.0000x reference)
#include <cuda_runtime.h>
#include <stdint.h>

// VDEmbedding: out[b,s,:] = (x[b,s]==0 ? 0 : mask[x[b,s]]) * weight[x[b,s], :]
// x: int32 [16,4096] (JAX default int, despite int64 in source), weight: f32 [128000,128],
// mask: f32 [128000] -> out: f32 [16,4096,128]

static constexpr int EMBED_DIM = 128;
static constexpr int PAD_IDX = 0;

__global__ __launch_bounds__(256, 8)
void vdemb_kernel(const int* __restrict__ x,
                  const float* __restrict__ weight,
                  const float* __restrict__ mask,
                  float* __restrict__ out,
                  int n_tokens)
{
    // one warp per token; lane handles one float4 (4 floats), 32*4 = 128 = EMBED_DIM
    int warp_in_block = threadIdx.x >> 5;
    int lane = threadIdx.x & 31;
    int token = blockIdx.x * (blockDim.x >> 5) + warp_in_block;
    if (token >= n_tokens) return;

    int idx = x[token];
    // pad semantics: zero out (weight row 0 is zero anyway, but be exact).
    float s = (idx == PAD_IDX) ? 0.0f : mask[idx];

    const float4* wrow = reinterpret_cast<const float4*>(weight + (size_t)idx * EMBED_DIM);
    float4* orow = reinterpret_cast<float4*>(out + (size_t)token * EMBED_DIM);

    float4 w = wrow[lane];
    float4 o;
    o.x = s * w.x;
    o.y = s * w.y;
    o.z = s * w.z;
    o.w = s * w.w;
    orow[lane] = o;
}

extern "C" void kernel_launch(void* const* d_in, const int* in_sizes, int n_in,
                              void* d_out, int out_size)
{
    // metadata order matches setup_inputs(): x (int32), weight (f32), mask (f32)
    const int*   x      = (const int*)d_in[0];
    const float* weight = (const float*)d_in[1];
    const float* mask   = (const float*)d_in[2];
    float*       out    = (float*)d_out;

    int n_tokens = in_sizes[0];           // 16*4096 = 65536
    int warps_per_block = 256 / 32;       // 8 tokens per block
    int blocks = (n_tokens + warps_per_block - 1) / warps_per_block;

    vdemb_kernel<<<blocks, 256>>>(x, weight, mask, out, n_tokens);
}